// round 9
// baseline (speedup 1.0000x reference)
#include <cuda_runtime.h>
#include <math.h>

#define MM 48
#define LL 48
#define NN 256
#define NPAIR 1176
#define NT 256            // threads per CTA (= per sample)
#define ZPJ 5             // pairs per thread (256*5 = 1280)
#define SLOTS 1280
#define CPB 12            // checkpoint rows: cp[b] = SUF(4b+3)

// smem (floats): ab float2[2304] | cp [12*1280] | u[48] | prt[2*48]
#define SM_AB  0
#define SM_CP  (2 * LL * MM)
#define SM_U   (SM_CP + CPB * SLOTS)
#define SM_PRT (SM_U + LL)
#define SMEMF  (SM_PRT + 96)

typedef unsigned long long u64;

// Accurate f32 sincos: Cody-Waite FMA range reduction + Taylor polys.
// |x| < ~80, ~1-2 ulp, immune to --use_fast_math (no libm).
__device__ __forceinline__ void sincos_acc(float x, float* s, float* c) {
    float kf = rintf(x * 0.63661977236758134f);
    int k = (int)kf;
    float r = fmaf(kf, -1.57079637050628662109375f, x);
    r = fmaf(kf, 4.37113882867379290e-8f, r);
    float r2 = r * r;
    float ps = fmaf(r2, 2.7557314297e-06f, -1.9841270114e-04f);
    ps = fmaf(r2, ps, 8.3333337680e-03f);
    ps = fmaf(r2, ps, -1.6666667163e-01f);
    float sr = fmaf(r * r2, ps, r);
    float pc = fmaf(r2, -2.7557314297e-07f, 2.4760126951e-05f);
    pc = fmaf(r2, pc, -1.3888889225e-03f);
    pc = fmaf(r2, pc, 4.1666667908e-02f);
    float cr = fmaf(r2 * r2, pc, fmaf(r2, -0.5f, 1.0f));
    switch (k & 3) {
        case 0: *s = sr;  *c = cr;  break;
        case 1: *s = cr;  *c = -sr; break;
        case 2: *s = -sr; *c = -cr; break;
        default:*s = -cr; *c = sr;  break;
    }
}

__global__ __launch_bounds__(NT, 2) void fused_kernel(
    const float* __restrict__ inp,      // (N,L)
    const float* __restrict__ theta,    // (L,M)
    const float* __restrict__ coef,     // (M,)
    const float* __restrict__ rand_u,   // (L,N)
    float* __restrict__ out)            // N*L bits then N probs
{
    extern __shared__ float sm[];
    float2* ab  = reinterpret_cast<float2*>(sm + SM_AB);
    float*  cp  = sm + SM_CP;
    float*  ush = sm + SM_U;
    float*  prt = sm + SM_PRT;

    const int n = blockIdx.x, tid = threadIdx.x;
    const int lane = tid & 31, wid = tid >> 5;

    // ---- Phase A: embedding tile (f32 rounding matches reference) ----
    const float PI2F = 1.57079637050628662109375f;
#pragma unroll
    for (int e = tid; e < LL * MM; e += NT) {
        int l = e / MM, m = e % MM;
        float ang = inp[n * LL + l] * ((float)(m + 1) * PI2F);
        float sa, ca; sincos_acc(ang, &sa, &ca);
        float st, ct; sincos_acc(theta[e], &st, &ct);
        float cf = coef[m];
        ab[e] = make_float2(cf * (ct * ca - st * sa),
                            cf * (st * ca + ct * sa));
    }
    if (tid < LL) ush[tid] = rand_u[tid * NN + n];
    __syncthreads();

    // ---- pair decode: 5 contiguous triangle pairs per thread ----
    int pmk[ZPJ]; float P[ZPJ];
    {
        int p0 = tid * ZPJ;
        int pc = (p0 < NPAIR) ? p0 : (NPAIR - 1);
        int m = 0, off = 0;
        while (off + (MM - m) <= pc) { off += MM - m; m++; }
        int k = m + (pc - off);
#pragma unroll
        for (int j = 0; j < ZPJ; j++) {
            int valid = (p0 + j < NPAIR);
            pmk[j] = valid ? (m | (k << 8)) : (47 | (47 << 8));
            P[j] = valid ? 1.0f : 0.0f;
            if (++k == MM) { ++m; k = m; }
            if (m >= MM) { m = MM - 1; k = MM - 1; }
        }
    }

    // ---- Phase B: backward scan; checkpoint SUF (weight baked) at l%4==3 ----
    {
        float run[ZPJ];
#pragma unroll
        for (int j = 0; j < ZPJ; j++) {
            int m = pmk[j] & 0xFF, k = pmk[j] >> 8;
            run[j] = (P[j] == 0.0f) ? 0.0f : ((m == k) ? 1.0f : 2.0f);
        }
        for (int l = LL - 1; l >= 0; l--) {
            if ((l & 3) == 3) {
                float* row = cp + (l >> 2) * SLOTS + tid * ZPJ;
#pragma unroll
                for (int j = 0; j < ZPJ; j++) row[j] = run[j];
            }
            const float2* abl = ab + l * MM;
#pragma unroll
            for (int j = 0; j < ZPJ; j++) {
                float2 vm = abl[pmk[j] & 0xFF];
                float2 vk = abl[pmk[j] >> 8];
                run[j] *= fmaf(vm.x, vk.x, vm.y * vk.y);
            }
        }
    }
    __syncthreads();

    // ---- init suffix rows for round 0: sufc=SUF(0), sufd=SUF(1) ----
    float sufc[ZPJ], sufd[ZPJ];
    {
        const float2* a3 = ab + 3 * MM;
        const float2* a2 = ab + 2 * MM;
        const float2* a1 = ab + 1 * MM;
        const float* c0 = cp + tid * ZPJ;
#pragma unroll
        for (int j = 0; j < ZPJ; j++) {
            int m = pmk[j] & 0xFF, k = pmk[j] >> 8;
            float2 vm = a3[m], vk = a3[k];
            float x = c0[j] * fmaf(vm.x, vk.x, vm.y * vk.y);   // SUF(2)
            vm = a2[m]; vk = a2[k];
            sufd[j] = x * fmaf(vm.x, vk.x, vm.y * vk.y);        // SUF(1)
            vm = a1[m]; vk = a1[k];
            sufc[j] = sufd[j] * fmaf(vm.x, vk.x, vm.y * vk.y);  // SUF(0)
        }
    }

    float denom0 = 1.0f;
    int Kexp = 0;
    u64 bits = 0ull;

    // ---- Phase C: 24 rounds, 2 sites per round ----
#pragma unroll 1
    for (int b = 0; b < CPB; b++) {
#pragma unroll
        for (int half = 0; half < 2; half++) {
            const int l = 4 * b + 2 * half;
            const float2* bl = ab + l * MM;

            float pa[ZPJ], pb[ZPJ], aa2[ZPJ], bb2[ZPJ];
            float s0 = 0.f, s1 = 0.f;
            float t00 = 0.f, t01 = 0.f, t10 = 0.f, t11 = 0.f;
#pragma unroll
            for (int j = 0; j < ZPJ; j++) {
                int m = pmk[j] & 0xFF, k = pmk[j] >> 8;
                float2 vm = bl[m],      vk = bl[k];        // site l
                float2 wm = bl[MM + m], wk = bl[MM + k];   // site l+1
                float aa1 = vm.x * vk.x, bb1 = vm.y * vk.y;
                aa2[j] = wm.x * wk.x;  bb2[j] = wm.y * wk.y;
                pa[j] = P[j] * aa1;    pb[j] = P[j] * bb1;
                s0 = fmaf(pa[j], sufc[j], s0);
                s1 = fmaf(pb[j], sufc[j], s1);
                float u0 = pa[j] * sufd[j], u1 = pb[j] * sufd[j];
                t00 = fmaf(u0, aa2[j], t00);
                t01 = fmaf(u0, bb2[j], t01);
                t10 = fmaf(u1, aa2[j], t10);
                t11 = fmaf(u1, bb2[j], t11);
            }
#pragma unroll
            for (int o = 16; o; o >>= 1) {
                s0  += __shfl_xor_sync(0xffffffffu, s0, o);
                s1  += __shfl_xor_sync(0xffffffffu, s1, o);
                t00 += __shfl_xor_sync(0xffffffffu, t00, o);
                t01 += __shfl_xor_sync(0xffffffffu, t01, o);
                t10 += __shfl_xor_sync(0xffffffffu, t10, o);
                t11 += __shfl_xor_sync(0xffffffffu, t11, o);
            }
            const int par = half;           // round parity within block
            float* pr = prt + par * 48;
            if (lane == 0) {
                pr[0 * 8 + wid] = s0;  pr[1 * 8 + wid] = s1;
                pr[2 * 8 + wid] = t00; pr[3 * 8 + wid] = t01;
                pr[4 * 8 + wid] = t10; pr[5 * 8 + wid] = t11;
            }

            // window: rebuild next round's suffix rows (bit-independent)
            if (half == 0) {
                // next sites (4b+2, 4b+3): sufd = cp[b], sufc = cp[b]*d(4b+3)
                const float2* a3 = ab + (4 * b + 3) * MM;
                const float* cb = cp + b * SLOTS + tid * ZPJ;
#pragma unroll
                for (int j = 0; j < ZPJ; j++) {
                    int m = pmk[j] & 0xFF, k = pmk[j] >> 8;
                    float2 vm = a3[m], vk = a3[k];
                    float c = cb[j];
                    sufd[j] = c;
                    sufc[j] = c * fmaf(vm.x, vk.x, vm.y * vk.y);
                }
            } else if (b + 1 < CPB) {
                // next sites (4b+4, 4b+5) from cp[b+1] = SUF(4b+7)
                const float2* a7 = ab + (4 * b + 7) * MM;
                const float2* a6 = ab + (4 * b + 6) * MM;
                const float2* a5 = ab + (4 * b + 5) * MM;
                const float* cb = cp + (b + 1) * SLOTS + tid * ZPJ;
#pragma unroll
                for (int j = 0; j < ZPJ; j++) {
                    int m = pmk[j] & 0xFF, k = pmk[j] >> 8;
                    float2 vm = a7[m], vk = a7[k];
                    float x = cb[j] * fmaf(vm.x, vk.x, vm.y * vk.y);   // SUF(4b+6)
                    vm = a6[m]; vk = a6[k];
                    sufd[j] = x * fmaf(vm.x, vk.x, vm.y * vk.y);        // SUF(4b+5)
                    vm = a5[m]; vk = a5[k];
                    sufc[j] = sufd[j] * fmaf(vm.x, vk.x, vm.y * vk.y);  // SUF(4b+4)
                }
            }
            __syncthreads();

            // redundant combine + double decision on all 256 threads
            float sum[6];
            const float4* q = reinterpret_cast<const float4*>(pr);
#pragma unroll
            for (int s = 0; s < 6; s++) {
                float4 v0 = q[2 * s], v1 = q[2 * s + 1];
                sum[s] = ((v0.x + v0.y) + (v0.z + v0.w))
                       + ((v1.x + v1.y) + (v1.z + v1.w));
            }
            float den1 = fabsf(sum[0] + sum[1]);
            int b1 = (ush[l] * den1 < fabsf(sum[1])) ? 1 : 0;
            if (l == 0) denom0 = den1;
            float S0p = b1 ? sum[4] : sum[2];
            float S1p = b1 ? sum[5] : sum[3];
            float den2 = fabsf(S0p + S1p);
            int b2 = (ush[l + 1] * den2 < fabsf(S1p)) ? 1 : 0;
            int eb = (__float_as_int(den2) >> 23) & 0xFF;   // exact 2^-k renorm
            int kk = eb ? (eb - 127) >> 1 : 0;
            Kexp += kk;
            float scale = __int_as_float((127 - kk) << 23);
            bits |= ((u64)b1 << l) | ((u64)b2 << (l + 1));
#pragma unroll
            for (int j = 0; j < ZPJ; j++) {
                float c1 = b1 ? pb[j] : pa[j];
                float c2 = b2 ? bb2[j] : aa2[j];
                P[j] = c1 * c2 * scale;
            }
        }
    }

    // ---- epilogue: final inner = sum w*P (true value * 2^Kexp), outputs ----
    float sf = 0.0f;
#pragma unroll
    for (int j = 0; j < ZPJ; j++) {
        int m = pmk[j] & 0xFF, k = pmk[j] >> 8;
        sf += ((m == k) ? 1.0f : 2.0f) * P[j];   // pads: P=0
    }
#pragma unroll
    for (int o = 16; o; o >>= 1) sf += __shfl_xor_sync(0xffffffffu, sf, o);
    if (lane == 0) prt[wid] = sf;
    __syncthreads();

    if (tid < LL) out[n * LL + tid] = (float)((bits >> tid) & 1ull);
    if (tid == 0) {
        float t = 0.f;
#pragma unroll
        for (int w = 0; w < 8; w++) t += prt[w];
        double pmv = ldexp(fabs((double)t), Kexp) / (double)denom0;
        out[NN * LL + n] = (float)pmv;
    }
}

extern "C" void kernel_launch(void* const* d_in, const int* in_sizes, int n_in,
                              void* d_out, int out_size) {
    const float* inp    = (const float*)d_in[0];   // (N,L)
    const float* theta  = (const float*)d_in[1];   // (L,M)
    const float* coef   = (const float*)d_in[2];   // (M,)
    const float* rand_u = (const float*)d_in[3];   // (L,N)
    float* out = (float*)d_out;

    static int smem_set = 0;
    if (!smem_set) {
        cudaFuncSetAttribute(fused_kernel,
                             cudaFuncAttributeMaxDynamicSharedMemorySize,
                             SMEMF * (int)sizeof(float));
        smem_set = 1;
    }
    fused_kernel<<<NN, NT, SMEMF * sizeof(float)>>>(inp, theta, coef, rand_u, out);
}

// round 10
// speedup vs baseline: 1.0558x; 1.0558x over previous
#include <cuda_runtime.h>
#include <math.h>

#define MM 48
#define LL 48
#define NN 256
#define NPAIR 1176
#define NT 128            // threads per CTA; CTA handles TWO samples
#define ZPJ 10            // pairs per thread (128*10 = 1280 slots)
#define SLOTS 1280
#define CPB 12            // checkpoint rows: cp[b] = SUF(4b+3)

// smem floats: abA(4608) | abB(4608) | cpA(15360) | cpB(15360) | uA(48) | uB(48) | prt(32)
#define SM_ABA 0
#define SM_ABB 4608
#define SM_CPA 9216
#define SM_CPB (SM_CPA + CPB * SLOTS)
#define SM_UA  (SM_CPB + CPB * SLOTS)
#define SM_UB  (SM_UA + LL)
#define SM_PRT (SM_UB + LL)
#define SMEMF  (SM_PRT + 32)

typedef unsigned long long u64;

// Accurate f32 sincos: Cody-Waite FMA range reduction + Taylor polys.
// |x| < ~80, ~1-2 ulp, immune to --use_fast_math (no libm).
__device__ __forceinline__ void sincos_acc(float x, float* s, float* c) {
    float kf = rintf(x * 0.63661977236758134f);
    int k = (int)kf;
    float r = fmaf(kf, -1.57079637050628662109375f, x);
    r = fmaf(kf, 4.37113882867379290e-8f, r);
    float r2 = r * r;
    float ps = fmaf(r2, 2.7557314297e-06f, -1.9841270114e-04f);
    ps = fmaf(r2, ps, 8.3333337680e-03f);
    ps = fmaf(r2, ps, -1.6666667163e-01f);
    float sr = fmaf(r * r2, ps, r);
    float pc = fmaf(r2, -2.7557314297e-07f, 2.4760126951e-05f);
    pc = fmaf(r2, pc, -1.3888889225e-03f);
    pc = fmaf(r2, pc, 4.1666667908e-02f);
    float cr = fmaf(r2 * r2, pc, fmaf(r2, -0.5f, 1.0f));
    switch (k & 3) {
        case 0: *s = sr;  *c = cr;  break;
        case 1: *s = cr;  *c = -sr; break;
        case 2: *s = -sr; *c = -cr; break;
        default:*s = -cr; *c = sr;  break;
    }
}

__global__ __launch_bounds__(NT, 1) void fused_kernel(
    const float* __restrict__ inp,      // (N,L)
    const float* __restrict__ theta,    // (L,M)
    const float* __restrict__ coef,     // (M,)
    const float* __restrict__ rand_u,   // (L,N)
    float* __restrict__ out)            // N*L bits then N probs
{
    extern __shared__ float sm[];
    float2* abA = reinterpret_cast<float2*>(sm + SM_ABA);
    float2* abB = reinterpret_cast<float2*>(sm + SM_ABB);
    float*  cpA = sm + SM_CPA;
    float*  cpB = sm + SM_CPB;
    float*  uA  = sm + SM_UA;
    float*  uB  = sm + SM_UB;
    float*  prt = sm + SM_PRT;

    const int tid = threadIdx.x;
    const int lane = tid & 31, wid = tid >> 5;
    const int n0 = blockIdx.x * 2, n1 = n0 + 1;

    // ---- Phase A: embedding tiles for BOTH samples (theta trig shared) ----
    const float PI2F = 1.57079637050628662109375f;
#pragma unroll
    for (int e = tid; e < LL * MM; e += NT) {
        int l = e / MM, m = e % MM;
        float st, ct; sincos_acc(theta[e], &st, &ct);
        float cf = coef[m];
        float km = (float)(m + 1) * PI2F;
        float sa, ca;
        sincos_acc(inp[n0 * LL + l] * km, &sa, &ca);
        abA[e] = make_float2(cf * (ct * ca - st * sa), cf * (st * ca + ct * sa));
        sincos_acc(inp[n1 * LL + l] * km, &sa, &ca);
        abB[e] = make_float2(cf * (ct * ca - st * sa), cf * (st * ca + ct * sa));
    }
    if (tid < LL) { uA[tid] = rand_u[tid * NN + n0]; uB[tid] = rand_u[tid * NN + n1]; }
    __syncthreads();

    // ---- pair decode: 10 contiguous triangle pairs per thread ----
    int pmk[ZPJ]; float w0[ZPJ];
    {
        int p0 = tid * ZPJ;
        int pc = (p0 < NPAIR) ? p0 : (NPAIR - 1);
        int m = 0, off = 0;
        while (off + (MM - m) <= pc) { off += MM - m; m++; }
        int k = m + (pc - off);
#pragma unroll
        for (int j = 0; j < ZPJ; j++) {
            int valid = (p0 + j < NPAIR);
            pmk[j] = valid ? (m | (k << 8)) : (47 | (47 << 8));
            w0[j] = valid ? ((m == k) ? 1.0f : 2.0f) : 0.0f;
            if (++k == MM) { ++m; k = m; }
            if (m >= MM) { m = MM - 1; k = MM - 1; }
        }
    }

    // ---- Phase B: backward scans (both samples, ILP-interleaved) ----
    {
        float runA[ZPJ], runB[ZPJ];
#pragma unroll
        for (int j = 0; j < ZPJ; j++) { runA[j] = w0[j]; runB[j] = w0[j]; }
        for (int l = LL - 1; l >= 0; l--) {
            if ((l & 3) == 3) {
                float* ra = cpA + (l >> 2) * SLOTS + tid * ZPJ;
                float* rb = cpB + (l >> 2) * SLOTS + tid * ZPJ;
#pragma unroll
                for (int j = 0; j < ZPJ; j++) { ra[j] = runA[j]; rb[j] = runB[j]; }
            }
            const float2* la = abA + l * MM;
            const float2* lb = abB + l * MM;
#pragma unroll
            for (int j = 0; j < ZPJ; j++) {
                int m = pmk[j] & 0xFF, k = pmk[j] >> 8;
                float2 vm = la[m], vk = la[k];
                runA[j] *= fmaf(vm.x, vk.x, vm.y * vk.y);
                vm = lb[m]; vk = lb[k];
                runB[j] *= fmaf(vm.x, vk.x, vm.y * vk.y);
            }
        }
    }
    // cp rows are written and read by the same thread — no barrier needed here.

    float rA[4][ZPJ], rB[4][ZPJ];
    float PA[ZPJ], PB[ZPJ];
#pragma unroll
    for (int j = 0; j < ZPJ; j++) { PA[j] = (w0[j] != 0.f) ? 1.f : 0.f; PB[j] = PA[j]; }

    // rebuild suffix rows for block b: r3=cp[b]=SUF(4b+3), r2=r3*d(4b+3), ...
    auto rebuild = [&](int b) {
        const float* ca = cpA + b * SLOTS + tid * ZPJ;
        const float* cb = cpB + b * SLOTS + tid * ZPJ;
        const float2* a3 = abA + (4 * b + 3) * MM; const float2* b3 = abB + (4 * b + 3) * MM;
        const float2* a2 = abA + (4 * b + 2) * MM; const float2* b2 = abB + (4 * b + 2) * MM;
        const float2* a1 = abA + (4 * b + 1) * MM; const float2* b1 = abB + (4 * b + 1) * MM;
#pragma unroll
        for (int j = 0; j < ZPJ; j++) {
            int m = pmk[j] & 0xFF, k = pmk[j] >> 8;
            rA[3][j] = ca[j];
            rB[3][j] = cb[j];
            float2 vm = a3[m], vk = a3[k];
            rA[2][j] = rA[3][j] * fmaf(vm.x, vk.x, vm.y * vk.y);
            vm = b3[m]; vk = b3[k];
            rB[2][j] = rB[3][j] * fmaf(vm.x, vk.x, vm.y * vk.y);
            vm = a2[m]; vk = a2[k];
            rA[1][j] = rA[2][j] * fmaf(vm.x, vk.x, vm.y * vk.y);
            vm = b2[m]; vk = b2[k];
            rB[1][j] = rB[2][j] * fmaf(vm.x, vk.x, vm.y * vk.y);
            vm = a1[m]; vk = a1[k];
            rA[0][j] = rA[1][j] * fmaf(vm.x, vk.x, vm.y * vk.y);
            vm = b1[m]; vk = b1[k];
            rB[0][j] = rB[1][j] * fmaf(vm.x, vk.x, vm.y * vk.y);
        }
    };
    rebuild(0);

    float denom0A = 1.f, denom0B = 1.f;
    int KexpA = 0, KexpB = 0;
    u64 bitsA = 0ull, bitsB = 0ull;

    // ---- Phase C: 48 steps, both samples per step (ILP overlap) ----
#pragma unroll 1
    for (int b = 0; b < CPB; b++) {
#pragma unroll
        for (int li = 0; li < 4; li++) {
            const int l = 4 * b + li;
            float uvA = uA[l], uvB = uB[l];          // prefetched (post-bar use)
            const float2* la = abA + l * MM;
            const float2* lb = abB + l * MM;

            float paA[ZPJ], pbA[ZPJ], paB[ZPJ], pbB[ZPJ];
            float s0A = 0.f, s1A = 0.f, e0A = 0.f, e1A = 0.f;
            float s0B = 0.f, s1B = 0.f, e0B = 0.f, e1B = 0.f;
#pragma unroll
            for (int j = 0; j < ZPJ; j++) {
                int m = pmk[j] & 0xFF, k = pmk[j] >> 8;
                float2 vm = la[m], vk = la[k];
                float aa = vm.x * vk.x, bb = vm.y * vk.y;
                paA[j] = PA[j] * aa; pbA[j] = PA[j] * bb;
                if (j & 1) { e0A = fmaf(paA[j], rA[li][j], e0A);
                             e1A = fmaf(pbA[j], rA[li][j], e1A); }
                else       { s0A = fmaf(paA[j], rA[li][j], s0A);
                             s1A = fmaf(pbA[j], rA[li][j], s1A); }
                vm = lb[m]; vk = lb[k];
                aa = vm.x * vk.x; bb = vm.y * vk.y;
                paB[j] = PB[j] * aa; pbB[j] = PB[j] * bb;
                if (j & 1) { e0B = fmaf(paB[j], rB[li][j], e0B);
                             e1B = fmaf(pbB[j], rB[li][j], e1B); }
                else       { s0B = fmaf(paB[j], rB[li][j], s0B);
                             s1B = fmaf(pbB[j], rB[li][j], s1B); }
            }
            s0A += e0A; s1A += e1A; s0B += e0B; s1B += e1B;
#pragma unroll
            for (int o = 16; o; o >>= 1) {
                s0A += __shfl_xor_sync(0xffffffffu, s0A, o);
                s1A += __shfl_xor_sync(0xffffffffu, s1A, o);
                s0B += __shfl_xor_sync(0xffffffffu, s0B, o);
                s1B += __shfl_xor_sync(0xffffffffu, s1B, o);
            }
            const int par = (l & 1) * 16;
            if (lane == 0) {
                prt[par + wid]      = s0A;
                prt[par + 4 + wid]  = s1A;
                prt[par + 8 + wid]  = s0B;
                prt[par + 12 + wid] = s1B;
            }
            if (li == 3 && b + 1 < CPB) rebuild(b + 1);   // fills bar wait
            __syncthreads();

            // redundant decisions (identical on all threads)
            const float4* q = reinterpret_cast<const float4*>(prt + par);
            float4 v;
            v = q[0]; float S0A = (v.x + v.y) + (v.z + v.w);
            v = q[1]; float S1A = (v.x + v.y) + (v.z + v.w);
            v = q[2]; float S0B = (v.x + v.y) + (v.z + v.w);
            v = q[3]; float S1B = (v.x + v.y) + (v.z + v.w);

            float denA = fabsf(S0A + S1A);
            int bitA = (uvA * denA < fabsf(S1A)) ? 1 : 0;
            float denB = fabsf(S0B + S1B);
            int bitB = (uvB * denB < fabsf(S1B)) ? 1 : 0;
            if (l == 0) { denom0A = denA; denom0B = denB; }
            int ea = (__float_as_int(denA) >> 23) & 0xFF;   // exact 2^-k renorm
            int ka = ea ? (ea - 127) >> 1 : 0;
            KexpA += ka;
            float scA = __int_as_float((127 - ka) << 23);
            int ebb = (__float_as_int(denB) >> 23) & 0xFF;
            int kb = ebb ? (ebb - 127) >> 1 : 0;
            KexpB += kb;
            float scB = __int_as_float((127 - kb) << 23);
            bitsA |= (u64)bitA << l;
            bitsB |= (u64)bitB << l;
#pragma unroll
            for (int j = 0; j < ZPJ; j++) {                 // select + scale only
                PA[j] = (bitA ? pbA[j] : paA[j]) * scA;
                PB[j] = (bitB ? pbB[j] : paB[j]) * scB;
            }
        }
    }

    // ---- epilogue: final inners (true value * 2^Kexp) + outputs ----
    float sfA = 0.f, sfB = 0.f;
#pragma unroll
    for (int j = 0; j < ZPJ; j++) { sfA += w0[j] * PA[j]; sfB += w0[j] * PB[j]; }
#pragma unroll
    for (int o = 16; o; o >>= 1) {
        sfA += __shfl_xor_sync(0xffffffffu, sfA, o);
        sfB += __shfl_xor_sync(0xffffffffu, sfB, o);
    }
    if (lane == 0) { prt[wid] = sfA; prt[4 + wid] = sfB; }
    __syncthreads();

    if (tid < LL) out[n0 * LL + tid] = (float)((bitsA >> tid) & 1ull);
    if (tid >= 64 && tid < 64 + LL)
        out[n1 * LL + (tid - 64)] = (float)((bitsB >> (tid - 64)) & 1ull);
    if (tid == 0) {
        double Sf = (double)((prt[0] + prt[1]) + (prt[2] + prt[3]));
        out[NN * LL + n0] = (float)(ldexp(fabs(Sf), KexpA) / (double)denom0A);
    }
    if (tid == 64) {
        double Sf = (double)((prt[4] + prt[5]) + (prt[6] + prt[7]));
        out[NN * LL + n1] = (float)(ldexp(fabs(Sf), KexpB) / (double)denom0B);
    }
}

extern "C" void kernel_launch(void* const* d_in, const int* in_sizes, int n_in,
                              void* d_out, int out_size) {
    const float* inp    = (const float*)d_in[0];   // (N,L)
    const float* theta  = (const float*)d_in[1];   // (L,M)
    const float* coef   = (const float*)d_in[2];   // (M,)
    const float* rand_u = (const float*)d_in[3];   // (L,N)
    float* out = (float*)d_out;

    static int smem_set = 0;
    if (!smem_set) {
        cudaFuncSetAttribute(fused_kernel,
                             cudaFuncAttributeMaxDynamicSharedMemorySize,
                             SMEMF * (int)sizeof(float));
        smem_set = 1;
    }
    fused_kernel<<<NN / 2, NT, SMEMF * sizeof(float)>>>(inp, theta, coef, rand_u, out);
}

// round 11
// speedup vs baseline: 1.4297x; 1.3542x over previous
#include <cuda_runtime.h>
#include <math.h>

#define MM 48
#define LL 48
#define NN 256
#define NT 128            // threads per CTA (= per sample)
#define KPJ 12            // k's per thread (4-aligned contiguous segment)
#define STR 60            // padded row stride for sa/sb (16B-aligned float4s)
#define SLOTS (NT * KPJ)  // 1536 checkpoint slots
#define CPB 12            // checkpoint rows: cp[b] = SUF(4b+3)

// smem floats: sa[48*60] | sb[48*60] | cp[12*1536] | u[48] | prt[24]
#define SM_SA  0
#define SM_SB  (LL * STR)
#define SM_CP  (2 * LL * STR)
#define SM_U   (SM_CP + CPB * SLOTS)
#define SM_PRT (SM_U + LL)
#define SMEMF  (SM_PRT + 24)

typedef unsigned long long u64;

// Accurate f32 sincos: Cody-Waite FMA range reduction + Taylor polys.
// |x| < ~80, ~1-2 ulp, immune to --use_fast_math (no libm).
__device__ __forceinline__ void sincos_acc(float x, float* s, float* c) {
    float kf = rintf(x * 0.63661977236758134f);
    int k = (int)kf;
    float r = fmaf(kf, -1.57079637050628662109375f, x);
    r = fmaf(kf, 4.37113882867379290e-8f, r);
    float r2 = r * r;
    float ps = fmaf(r2, 2.7557314297e-06f, -1.9841270114e-04f);
    ps = fmaf(r2, ps, 8.3333337680e-03f);
    ps = fmaf(r2, ps, -1.6666667163e-01f);
    float sr = fmaf(r * r2, ps, r);
    float pc = fmaf(r2, -2.7557314297e-07f, 2.4760126951e-05f);
    pc = fmaf(r2, pc, -1.3888889225e-03f);
    pc = fmaf(r2, pc, 4.1666667908e-02f);
    float cr = fmaf(r2 * r2, pc, fmaf(r2, -0.5f, 1.0f));
    switch (k & 3) {
        case 0: *s = sr;  *c = cr;  break;
        case 1: *s = cr;  *c = -sr; break;
        case 2: *s = -sr; *c = -cr; break;
        default:*s = -cr; *c = sr;  break;
    }
}

// 12 aligned floats -> regs (3x LDS.128)
__device__ __forceinline__ void ld12(const float* p, float* v) {
    const float4* q = reinterpret_cast<const float4*>(p);
    float4 x = q[0], y = q[1], z = q[2];
    v[0] = x.x; v[1] = x.y; v[2]  = x.z; v[3]  = x.w;
    v[4] = y.x; v[5] = y.y; v[6]  = y.z; v[7]  = y.w;
    v[8] = z.x; v[9] = z.y; v[10] = z.z; v[11] = z.w;
}
__device__ __forceinline__ void st12(float* p, const float* v) {
    float4* q = reinterpret_cast<float4*>(p);
    q[0] = make_float4(v[0], v[1], v[2],  v[3]);
    q[1] = make_float4(v[4], v[5], v[6],  v[7]);
    q[2] = make_float4(v[8], v[9], v[10], v[11]);
}

__global__ __launch_bounds__(NT, 2) void fused_kernel(
    const float* __restrict__ inp,      // (N,L)
    const float* __restrict__ theta,    // (L,M)
    const float* __restrict__ coef,     // (M,)
    const float* __restrict__ rand_u,   // (L,N)
    float* __restrict__ out)            // N*L bits then N probs
{
    extern __shared__ float sm[];
    float* sa  = sm + SM_SA;    // a values, row stride 60, cols 48..59 = 0
    float* sb  = sm + SM_SB;
    float* cp  = sm + SM_CP;
    float* ush = sm + SM_U;
    float* prt = sm + SM_PRT;

    const int n = blockIdx.x, tid = threadIdx.x;
    const int lane = tid & 31, wid = tid >> 5;

    // ---- Phase A: SoA embedding tiles (f32 rounding matches reference) ----
    const float PI2F = 1.57079637050628662109375f;
#pragma unroll
    for (int e = tid; e < LL * STR; e += NT) {
        int l = e / STR, c = e - l * STR;
        float a = 0.f, b = 0.f;
        if (c < MM) {
            float ang = inp[n * LL + l] * ((float)(c + 1) * PI2F);
            float sv, cv; sincos_acc(ang, &sv, &cv);
            float st, ct; sincos_acc(theta[l * MM + c], &st, &ct);
            float cf = coef[c];
            a = cf * (ct * cv - st * sv);
            b = cf * (st * cv + ct * sv);
        }
        sa[e] = a; sb[e] = b;
    }
    if (tid < LL) ush[tid] = rand_u[tid * NN + n];
    __syncthreads();

    // ---- segment decode: thread owns m and k in [kst, kst+11], kst % 4 == 0 ----
    int m = 47, kst = 48;                 // default: idle thread (reads zero pad)
    {
        int t = tid;
        for (int mm = 0; mm < MM; mm++) {
            int s = mm & ~3;
            int nseg = (MM - s + KPJ - 1) / KPJ;
            if (t < nseg) { m = mm; kst = s + t * KPJ; break; }
            t -= nseg;
        }
    }
    // weight per slot: 0 if k<m or k>=48 (dup/pad), 1 if k==m, else 2
    float w0[KPJ];
#pragma unroll
    for (int j = 0; j < KPJ; j++) {
        int k = kst + j;
        w0[j] = (k < m || k >= MM) ? 0.f : ((k == m) ? 1.f : 2.f);
    }

    // ---- Phase B: backward scan; checkpoint SUF (weight baked) at l%4==3 ----
    {
        float run[KPJ];
#pragma unroll
        for (int j = 0; j < KPJ; j++) run[j] = w0[j];
        for (int l = LL - 1; l >= 0; l--) {
            if ((l & 3) == 3)
                st12(cp + (l >> 2) * SLOTS + tid * KPJ, run);
            float am = sa[l * STR + m], bm = sb[l * STR + m];
            float ak[KPJ], bk[KPJ];
            ld12(sa + l * STR + kst, ak);
            ld12(sb + l * STR + kst, bk);
#pragma unroll
            for (int j = 0; j < KPJ; j++)
                run[j] *= fmaf(am, ak[j], bm * bk[j]);
        }
    }
    // cp rows written and read by the same thread — no barrier needed.

    float P[KPJ];
#pragma unroll
    for (int j = 0; j < KPJ; j++) P[j] = (w0[j] != 0.f) ? 1.f : 0.f;

    float r0[KPJ], r1[KPJ], r2[KPJ], r3[KPJ];
    auto rebuild = [&](int b) {
        ld12(cp + b * SLOTS + tid * KPJ, r3);          // SUF(4b+3)
        float ak[KPJ], bk[KPJ];
        int l = 4 * b + 3;
        float am = sa[l * STR + m], bm = sb[l * STR + m];
        ld12(sa + l * STR + kst, ak); ld12(sb + l * STR + kst, bk);
#pragma unroll
        for (int j = 0; j < KPJ; j++) r2[j] = r3[j] * fmaf(am, ak[j], bm * bk[j]);
        l = 4 * b + 2;
        am = sa[l * STR + m]; bm = sb[l * STR + m];
        ld12(sa + l * STR + kst, ak); ld12(sb + l * STR + kst, bk);
#pragma unroll
        for (int j = 0; j < KPJ; j++) r1[j] = r2[j] * fmaf(am, ak[j], bm * bk[j]);
        l = 4 * b + 1;
        am = sa[l * STR + m]; bm = sb[l * STR + m];
        ld12(sa + l * STR + kst, ak); ld12(sb + l * STR + kst, bk);
#pragma unroll
        for (int j = 0; j < KPJ; j++) r0[j] = r1[j] * fmaf(am, ak[j], bm * bk[j]);
    };
    rebuild(0);

    float denom0 = 1.f;
    int Kexp = 0;
    u64 bits = 0ull;

    // ---- Phase C: 48 steps; speculative pa/pb; one barrier per step ----
#pragma unroll 1
    for (int b = 0; b < CPB; b++) {
#pragma unroll
        for (int li = 0; li < 4; li++) {
            const int l = 4 * b + li;
            const float* rr = (li == 0) ? r0 : (li == 1) ? r1 : (li == 2) ? r2 : r3;
            float uv = ush[l];

            float am = sa[l * STR + m], bm = sb[l * STR + m];
            float ak[KPJ], bk[KPJ];
            ld12(sa + l * STR + kst, ak);
            ld12(sb + l * STR + kst, bk);

            float pa[KPJ], pb[KPJ];
            float s0 = 0.f, s1 = 0.f, e0 = 0.f, e1 = 0.f;
#pragma unroll
            for (int j = 0; j < KPJ; j++) {
                pa[j] = P[j] * (am * ak[j]);     // speculative bit=0 factor
                pb[j] = P[j] * (bm * bk[j]);     // speculative bit=1 factor
                if (j & 1) { e0 = fmaf(pa[j], rr[j], e0); e1 = fmaf(pb[j], rr[j], e1); }
                else       { s0 = fmaf(pa[j], rr[j], s0); s1 = fmaf(pb[j], rr[j], s1); }
            }
            s0 += e0; s1 += e1;
#pragma unroll
            for (int o = 16; o; o >>= 1) {
                s0 += __shfl_xor_sync(0xffffffffu, s0, o);
                s1 += __shfl_xor_sync(0xffffffffu, s1, o);
            }
            const int par = (l & 1) * 8;
            if (lane == 0) { prt[par + wid] = s0; prt[par + 4 + wid] = s1; }
            if (li == 3 && b + 1 < CPB) rebuild(b + 1);   // fills bar wait
            __syncthreads();

            // redundant decision (identical on all threads)
            const float4* q = reinterpret_cast<const float4*>(prt + par);
            float4 v0 = q[0], v1 = q[1];
            float S0 = (v0.x + v0.y) + (v0.z + v0.w);
            float S1 = (v1.x + v1.y) + (v1.z + v1.w);
            float den = fabsf(S0 + S1);
            int bit = (uv * den < fabsf(S1)) ? 1 : 0;     // u < |S1|/den
            if (l == 0) denom0 = den;
            int eb = (__float_as_int(den) >> 23) & 0xFF;  // exact 2^-k renorm
            int kk = eb ? (eb - 127) >> 1 : 0;
            Kexp += kk;
            float scale = __int_as_float((127 - kk) << 23);
            bits |= (u64)bit << l;
#pragma unroll
            for (int j = 0; j < KPJ; j++)                 // select + scale only
                P[j] = (bit ? pb[j] : pa[j]) * scale;
        }
    }

    // ---- epilogue: final inner = sum w*P (true value * 2^Kexp), outputs ----
    float sf = 0.f;
#pragma unroll
    for (int j = 0; j < KPJ; j++) sf += w0[j] * P[j];
#pragma unroll
    for (int o = 16; o; o >>= 1) sf += __shfl_xor_sync(0xffffffffu, sf, o);
    if (lane == 0) prt[16 + wid] = sf;
    __syncthreads();

    if (tid < LL) out[n * LL + tid] = (float)((bits >> tid) & 1ull);
    if (tid == 0) {
        double Sf = (double)((prt[16] + prt[17]) + (prt[18] + prt[19]));
        double pmv = ldexp(fabs(Sf), Kexp) / (double)denom0;
        out[NN * LL + n] = (float)pmv;
    }
}

extern "C" void kernel_launch(void* const* d_in, const int* in_sizes, int n_in,
                              void* d_out, int out_size) {
    const float* inp    = (const float*)d_in[0];   // (N,L)
    const float* theta  = (const float*)d_in[1];   // (L,M)
    const float* coef   = (const float*)d_in[2];   // (M,)
    const float* rand_u = (const float*)d_in[3];   // (L,N)
    float* out = (float*)d_out;

    static int smem_set = 0;
    if (!smem_set) {
        cudaFuncSetAttribute(fused_kernel,
                             cudaFuncAttributeMaxDynamicSharedMemorySize,
                             SMEMF * (int)sizeof(float));
        smem_set = 1;
    }
    fused_kernel<<<NN, NT, SMEMF * sizeof(float)>>>(inp, theta, coef, rand_u, out);
}

// round 12
// speedup vs baseline: 1.5942x; 1.1150x over previous
#include <cuda_runtime.h>
#include <math.h>

#define MM 48
#define LL 48
#define NN 256
#define NT 128            // threads per CTA (= per sample)
#define KPJ 12            // k's per thread (4-aligned contiguous segment)
#define STR 60            // padded row stride for sa/sb (16B-aligned float4s)
#define SLOTS (NT * KPJ)  // 1536 checkpoint slots
#define CPB 12            // checkpoint rows: cp[b] = SUF(4b+3)

// smem floats: sa[48*60] | sb[48*60] | cp[12*1536] | u[48] | prt[40]
#define SM_SA  0
#define SM_SB  (LL * STR)
#define SM_CP  (2 * LL * STR)
#define SM_U   (SM_CP + CPB * SLOTS)
#define SM_PRT (SM_U + LL)
#define SMEMF  (SM_PRT + 40)

typedef unsigned long long u64;

// Accurate f32 sincos: Cody-Waite FMA range reduction + Taylor polys.
// |x| < ~80, ~1-2 ulp, immune to --use_fast_math (no libm).
__device__ __forceinline__ void sincos_acc(float x, float* s, float* c) {
    float kf = rintf(x * 0.63661977236758134f);
    int k = (int)kf;
    float r = fmaf(kf, -1.57079637050628662109375f, x);
    r = fmaf(kf, 4.37113882867379290e-8f, r);
    float r2 = r * r;
    float ps = fmaf(r2, 2.7557314297e-06f, -1.9841270114e-04f);
    ps = fmaf(r2, ps, 8.3333337680e-03f);
    ps = fmaf(r2, ps, -1.6666667163e-01f);
    float sr = fmaf(r * r2, ps, r);
    float pc = fmaf(r2, -2.7557314297e-07f, 2.4760126951e-05f);
    pc = fmaf(r2, pc, -1.3888889225e-03f);
    pc = fmaf(r2, pc, 4.1666667908e-02f);
    float cr = fmaf(r2 * r2, pc, fmaf(r2, -0.5f, 1.0f));
    switch (k & 3) {
        case 0: *s = sr;  *c = cr;  break;
        case 1: *s = cr;  *c = -sr; break;
        case 2: *s = -sr; *c = -cr; break;
        default:*s = -cr; *c = sr;  break;
    }
}

// 12 aligned floats <-> regs (3x LDS/STS.128)
__device__ __forceinline__ void ld12(const float* p, float* v) {
    const float4* q = reinterpret_cast<const float4*>(p);
    float4 x = q[0], y = q[1], z = q[2];
    v[0] = x.x; v[1] = x.y; v[2]  = x.z; v[3]  = x.w;
    v[4] = y.x; v[5] = y.y; v[6]  = y.z; v[7]  = y.w;
    v[8] = z.x; v[9] = z.y; v[10] = z.z; v[11] = z.w;
}
__device__ __forceinline__ void st12(float* p, const float* v) {
    float4* q = reinterpret_cast<float4*>(p);
    q[0] = make_float4(v[0], v[1], v[2],  v[3]);
    q[1] = make_float4(v[4], v[5], v[6],  v[7]);
    q[2] = make_float4(v[8], v[9], v[10], v[11]);
}

__global__ __launch_bounds__(NT, 2) void fused_kernel(
    const float* __restrict__ inp,      // (N,L)
    const float* __restrict__ theta,    // (L,M)
    const float* __restrict__ coef,     // (M,)
    const float* __restrict__ rand_u,   // (L,N)
    float* __restrict__ out)            // N*L bits then N probs
{
    extern __shared__ float sm[];
    float* sa  = sm + SM_SA;    // a values, row stride 60, cols 48..59 = 0
    float* sb  = sm + SM_SB;
    float* cp  = sm + SM_CP;
    float* ush = sm + SM_U;
    float* prt = sm + SM_PRT;

    const int n = blockIdx.x, tid = threadIdx.x;
    const int lane = tid & 31, wid = tid >> 5;

    // ---- Phase A: SoA embedding tiles (f32 rounding matches reference) ----
    const float PI2F = 1.57079637050628662109375f;
#pragma unroll
    for (int e = tid; e < LL * STR; e += NT) {
        int l = e / STR, c = e - l * STR;
        float a = 0.f, b = 0.f;
        if (c < MM) {
            float ang = inp[n * LL + l] * ((float)(c + 1) * PI2F);
            float sv, cv; sincos_acc(ang, &sv, &cv);
            float st, ct; sincos_acc(theta[l * MM + c], &st, &ct);
            float cf = coef[c];
            a = cf * (ct * cv - st * sv);
            b = cf * (st * cv + ct * sv);
        }
        sa[e] = a; sb[e] = b;
    }
    if (tid < LL) ush[tid] = rand_u[tid * NN + n];
    __syncthreads();

    // ---- segment decode: thread owns m and k in [kst, kst+11], kst % 4 == 0 ----
    int m = 47, kst = 48;                 // default: idle thread (reads zero pad)
    {
        int t = tid;
        for (int mm = 0; mm < MM; mm++) {
            int s = mm & ~3;
            int nseg = (MM - s + KPJ - 1) / KPJ;
            if (t < nseg) { m = mm; kst = s + t * KPJ; break; }
            t -= nseg;
        }
    }

    // ---- Phase B: backward scan; checkpoint SUF (weight baked) at l%4==3 ----
    {
        float run[KPJ];
#pragma unroll
        for (int j = 0; j < KPJ; j++) {
            int k = kst + j;
            run[j] = (k < m || k >= MM) ? 0.f : ((k == m) ? 1.f : 2.f);
        }
        for (int l = LL - 1; l >= 0; l--) {
            if ((l & 3) == 3)
                st12(cp + (l >> 2) * SLOTS + tid * KPJ, run);
            float am = sa[l * STR + m], bm = sb[l * STR + m];
            float ak[KPJ], bk[KPJ];
            ld12(sa + l * STR + kst, ak);
            ld12(sb + l * STR + kst, bk);
#pragma unroll
            for (int j = 0; j < KPJ; j++)
                run[j] *= fmaf(am, ak[j], bm * bk[j]);
        }
    }
    // cp rows written and read by the same thread — no barrier needed.

    float P[KPJ];
#pragma unroll
    for (int j = 0; j < KPJ; j++)
        P[j] = (kst + j < m || kst + j >= MM) ? 0.f : 1.f;

    // suffix registers: r3 = SUF(4b+3) = cp[b]; r1 = SUF(4b+1) = r3*d(4b+3)*d(4b+2)
    float r1[KPJ], r3[KPJ];
    auto rebuild = [&](int b) {
        ld12(cp + b * SLOTS + tid * KPJ, r3);
        float ak[KPJ], bk[KPJ];
        int l = 4 * b + 3;
        float am = sa[l * STR + m], bm = sb[l * STR + m];
        ld12(sa + l * STR + kst, ak); ld12(sb + l * STR + kst, bk);
#pragma unroll
        for (int j = 0; j < KPJ; j++) r1[j] = r3[j] * fmaf(am, ak[j], bm * bk[j]);
        l = 4 * b + 2;
        am = sa[l * STR + m]; bm = sb[l * STR + m];
        ld12(sa + l * STR + kst, ak); ld12(sb + l * STR + kst, bk);
#pragma unroll
        for (int j = 0; j < KPJ; j++) r1[j] *= fmaf(am, ak[j], bm * bk[j]);
    };
    rebuild(0);

    float denom0 = 1.f;
    int Kexp = 0;
    u64 bits = 0ull;

    // ---- Phase C: 24 two-site rounds (4 speculative sums, 1 barrier each) ----
    // T_{b1,b2} = sum_j P*cc1_{b1}*cc2_{b2}*SUF(l0+1);  S_b(l0) = T_{b,0}+T_{b,1}.
    auto round2 = [&](int l0, const float* suf, int bnext) {
        float uv1 = ush[l0], uv2 = ush[l0 + 1];
        float am1 = sa[l0 * STR + m],       bm1 = sb[l0 * STR + m];
        float am2 = sa[(l0 + 1) * STR + m], bm2 = sb[(l0 + 1) * STR + m];
        float ak1[KPJ], bk1[KPJ], ak2[KPJ], bk2[KPJ];
        ld12(sa + l0 * STR + kst, ak1);
        ld12(sb + l0 * STR + kst, bk1);
        ld12(sa + (l0 + 1) * STR + kst, ak2);
        ld12(sb + (l0 + 1) * STR + kst, bk2);

        float q00[KPJ], q01[KPJ], q10[KPJ], q11[KPJ];
        float t00 = 0.f, t01 = 0.f, t10 = 0.f, t11 = 0.f;
#pragma unroll
        for (int j = 0; j < KPJ; j++) {
            float pa = P[j] * (am1 * ak1[j]);
            float pb = P[j] * (bm1 * bk1[j]);
            float aa2 = am2 * ak2[j], bb2 = bm2 * bk2[j];
            q00[j] = pa * aa2; q01[j] = pa * bb2;
            q10[j] = pb * aa2; q11[j] = pb * bb2;
            t00 = fmaf(q00[j], suf[j], t00);
            t01 = fmaf(q01[j], suf[j], t01);
            t10 = fmaf(q10[j], suf[j], t10);
            t11 = fmaf(q11[j], suf[j], t11);
        }
#pragma unroll
        for (int o = 16; o; o >>= 1) {
            t00 += __shfl_xor_sync(0xffffffffu, t00, o);
            t01 += __shfl_xor_sync(0xffffffffu, t01, o);
            t10 += __shfl_xor_sync(0xffffffffu, t10, o);
            t11 += __shfl_xor_sync(0xffffffffu, t11, o);
        }
        const int par = ((l0 >> 1) & 1) * 16;
        if (lane == 0) {
            prt[par + wid]      = t00;
            prt[par + 4 + wid]  = t01;
            prt[par + 8 + wid]  = t10;
            prt[par + 12 + wid] = t11;
        }
        if (bnext >= 0) rebuild(bnext);    // fills bar wait, bit-independent
        __syncthreads();

        // redundant decisions (identical on all threads)
        const float4* q = reinterpret_cast<const float4*>(prt + par);
        float4 v;
        v = q[0]; float T00 = (v.x + v.y) + (v.z + v.w);
        v = q[1]; float T01 = (v.x + v.y) + (v.z + v.w);
        v = q[2]; float T10 = (v.x + v.y) + (v.z + v.w);
        v = q[3]; float T11 = (v.x + v.y) + (v.z + v.w);

        float S1  = T10 + T11;
        float den1 = fabsf((T00 + T01) + S1);
        int b1 = (uv1 * den1 < fabsf(S1)) ? 1 : 0;
        if (l0 == 0) denom0 = den1;
        float S0p = b1 ? T10 : T00;
        float S1p = b1 ? T11 : T01;
        float den2 = fabsf(S0p + S1p);
        int b2 = (uv2 * den2 < fabsf(S1p)) ? 1 : 0;
        int eb = (__float_as_int(den2) >> 23) & 0xFF;   // exact 2^-k renorm
        int kk = eb ? (eb - 127) >> 1 : 0;
        Kexp += kk;
        float scale = __int_as_float((127 - kk) << 23);
        bits |= ((u64)b1 << l0) | ((u64)b2 << (l0 + 1));
#pragma unroll
        for (int j = 0; j < KPJ; j++) {                 // select + scale only
            float qa = b2 ? q01[j] : q00[j];
            float qb = b2 ? q11[j] : q10[j];
            P[j] = (b1 ? qb : qa) * scale;
        }
    };

#pragma unroll 1
    for (int b = 0; b < CPB; b++) {
        round2(4 * b,     r1, -1);
        round2(4 * b + 2, r3, (b + 1 < CPB) ? b + 1 : -1);
    }

    // ---- epilogue: final inner = sum w*P (true value * 2^Kexp), outputs ----
    float sf = 0.f;
#pragma unroll
    for (int j = 0; j < KPJ; j++) {
        int k = kst + j;
        float w = (k < m || k >= MM) ? 0.f : ((k == m) ? 1.f : 2.f);
        sf += w * P[j];
    }
#pragma unroll
    for (int o = 16; o; o >>= 1) sf += __shfl_xor_sync(0xffffffffu, sf, o);
    if (lane == 0) prt[32 + wid] = sf;
    __syncthreads();

    if (tid < LL) out[n * LL + tid] = (float)((bits >> tid) & 1ull);
    if (tid == 0) {
        double Sf = (double)((prt[32] + prt[33]) + (prt[34] + prt[35]));
        double pmv = ldexp(fabs(Sf), Kexp) / (double)denom0;
        out[NN * LL + n] = (float)pmv;
    }
}

extern "C" void kernel_launch(void* const* d_in, const int* in_sizes, int n_in,
                              void* d_out, int out_size) {
    const float* inp    = (const float*)d_in[0];   // (N,L)
    const float* theta  = (const float*)d_in[1];   // (L,M)
    const float* coef   = (const float*)d_in[2];   // (M,)
    const float* rand_u = (const float*)d_in[3];   // (L,N)
    float* out = (float*)d_out;

    static int smem_set = 0;
    if (!smem_set) {
        cudaFuncSetAttribute(fused_kernel,
                             cudaFuncAttributeMaxDynamicSharedMemorySize,
                             SMEMF * (int)sizeof(float));
        smem_set = 1;
    }
    fused_kernel<<<NN, NT, SMEMF * sizeof(float)>>>(inp, theta, coef, rand_u, out);
}